// round 8
// baseline (speedup 1.0000x reference)
#include <cuda_runtime.h>

#define N_NODES 100000
#define N_EDGES 3200000
#define IN_CH   512
#define HIDDEN  64
#define LOC_OUT 16
#define OUT_CH  40

// ---------------- scratch (static device globals; no runtime alloc) ----------
__device__ __align__(16) int   d_degi[N_NODES];            // edge in-degree (no self loop)
__device__ __align__(16) float d_dinv[N_NODES];            // 1/sqrt(deg+1)
__device__ __align__(16) float d_g1  [N_NODES * HIDDEN];   // dinv * (X @ W1)
__device__ __align__(16) float d_x1  [N_NODES * HIDDEN];   // relu layer-1 output
__device__ __align__(16) float d_g2  [N_NODES * LOC_OUT];  // dinv * (x1 @ W2)
__device__ __align__(16) float d_x2  [N_NODES * LOC_OUT];  // layer-2 output (z0)
__device__ __align__(16) int   d_off [N_NODES + 1];        // CSR offsets (by dst)
__device__ __align__(16) int   d_cur [N_NODES];            // placement cursors
__device__ __align__(16) int   d_src [N_EDGES];            // dst-sorted source ids
__device__ int d_idx_nonzero_odd;   // >0  =>  edge_index is int32

// ---------------- packed f32x2 helpers ---------------------------------------
__device__ __forceinline__ unsigned long long dup2(float a) {
    unsigned long long r;
    asm("mov.b64 %0, {%1, %1};" : "=l"(r) : "f"(a));
    return r;
}
__device__ __forceinline__ unsigned long long pack2(float lo, float hi) {
    unsigned long long r;
    asm("mov.b64 %0, {%1, %2};" : "=l"(r) : "f"(lo), "f"(hi));
    return r;
}
__device__ __forceinline__ void fma2(unsigned long long& d,
                                     unsigned long long a, unsigned long long b) {
    asm("fma.rn.f32x2 %0, %1, %2, %0;" : "+l"(d) : "l"(a), "l"(b));
}
__device__ __forceinline__ void unpack2(unsigned long long v, float& lo, float& hi) {
    asm("mov.b64 {%0, %1}, %2;" : "=f"(lo), "=f"(hi) : "l"(v));
}

// ---------------- edge index fetch: handles int64 or int32 buffers -----------
__device__ __forceinline__ int load_edge(const void* ei, unsigned int pos) {
    if (d_idx_nonzero_odd == 0) {          // int64 payload (high words all 0)
        return (int)((const long long*)ei)[pos];
    } else {                               // int32 payload
        return ((const int*)ei)[pos];
    }
}

// ---------------- dtype detection: sample odd int32 slots --------------------
__global__ void k_detect(const int* __restrict__ ei32) {
    int t = threadIdx.x;                   // 256 threads, 8 samples each
    int nz = 0;
    #pragma unroll
    for (int j = 0; j < 8; j++) nz |= ei32[2 * (t * 8 + j) + 1];
    if (nz) atomicOr(&d_idx_nonzero_odd, 1);
}

// ---------------- init: zero degree histogram + flag -------------------------
__global__ void k_init() {
    int i = blockIdx.x * blockDim.x + threadIdx.x;
    if (i < N_NODES) d_degi[i] = 0;
    if (i == 0)      d_idx_nonzero_odd = 0;
}

// ---------------- degree count over targets (col = edge_index[1]) ------------
__global__ void k_count(const void* __restrict__ ei) {
    unsigned int e = blockIdx.x * blockDim.x + threadIdx.x;
    if (e < N_EDGES) {
        int c = load_edge(ei, N_EDGES + e);
        if ((unsigned)c < N_NODES) atomicAdd(&d_degi[c], 1);
    }
}

// ---------------- GEMM1: g1 = dinv * (X @ W1);  also writes d_dinv -----------
// BM=256 rows x 64 cols per block, 256 threads, 8x8 per thread, FFMA2.
#define BM 256
#define BK 32
#define XS_STRIDE 33            // m-major: Xs[m*33 + k]; conflict-free LDS/STS

__global__ __launch_bounds__(256) void k_gemm1(const float* __restrict__ X,
                                               const float* __restrict__ W1) {
    __shared__ float Xs[BM * XS_STRIDE];   // 33.8 KB
    __shared__ float Ws[BK * HIDDEN];      // 8 KB, k-major: Ws[k*64 + n]
    int tid = threadIdx.x;
    int tx = tid & 7;          // col group: cols tx*8 .. tx*8+7
    int ty = tid >> 3;         // row group: rows ty*8 .. ty*8+7 (0..31)
    int row0 = blockIdx.x * BM;

    unsigned long long acc[8][4];
    #pragma unroll
    for (int i = 0; i < 8; i++)
        #pragma unroll
        for (int j = 0; j < 4; j++) acc[i][j] = 0ULL;

    for (int k0 = 0; k0 < IN_CH; k0 += BK) {
        // X tile (256 x 32): float4 global load, 4 conflict-free scalar stores
        #pragma unroll
        for (int it = 0; it < 8; it++) {
            int m  = (tid >> 3) + it * 32;     // 0..255
            int kq = (tid & 7) * 4;            // 0,4,...,28
            int gr = row0 + m;
            float4 v = (gr < N_NODES)
                     ? *(const float4*)&X[(size_t)gr * IN_CH + k0 + kq]
                     : make_float4(0.f, 0.f, 0.f, 0.f);
            float* xs = &Xs[m * XS_STRIDE + kq];
            xs[0] = v.x; xs[1] = v.y; xs[2] = v.z; xs[3] = v.w;
        }
        // W tile (32 x 64), contiguous float4 copy
        #pragma unroll
        for (int it = 0; it < 2; it++) {
            int f4 = tid + it * 256;
            ((float4*)Ws)[f4] = ((const float4*)&W1[(size_t)k0 * HIDDEN])[f4];
        }
        __syncthreads();

        #pragma unroll
        for (int k = 0; k < BK; k++) {
            const ulonglong2* bw = (const ulonglong2*)&Ws[k * HIDDEN + tx * 8];
            ulonglong2 bA = bw[0];
            ulonglong2 bB = bw[1];
            #pragma unroll
            for (int i = 0; i < 8; i++) {
                unsigned long long A = dup2(Xs[(ty * 8 + i) * XS_STRIDE + k]);
                fma2(acc[i][0], A, bA.x);
                fma2(acc[i][1], A, bA.y);
                fma2(acc[i][2], A, bB.x);
                fma2(acc[i][3], A, bB.y);
            }
        }
        __syncthreads();
    }

    // epilogue: dinv = rsqrt(deg+1) computed inline; scale + store
    #pragma unroll
    for (int i = 0; i < 8; i++) {
        int r = row0 + ty * 8 + i;
        if (r < N_NODES) {
            float di = rsqrtf((float)(d_degi[r] + 1));
            if (tx == 0) d_dinv[r] = di;
            float o[8];
            #pragma unroll
            for (int j = 0; j < 4; j++) unpack2(acc[i][j], o[2 * j], o[2 * j + 1]);
            float4 v0 = make_float4(di * o[0], di * o[1], di * o[2], di * o[3]);
            float4 v1 = make_float4(di * o[4], di * o[5], di * o[6], di * o[7]);
            float* dst = &d_g1[(size_t)r * HIDDEN + tx * 8];
            *(float4*)dst       = v0;
            *(float4*)(dst + 4) = v1;
        }
    }
}

// ---------------- exclusive scan of degrees -> CSR offsets (1 block) ---------
__global__ __launch_bounds__(1024) void k_scan() {
    __shared__ int s[1024];
    const int C = (N_NODES + 1023) / 1024;       // 98
    int t = threadIdx.x;
    int beg = t * C;
    int end = beg + C; if (end > N_NODES) end = N_NODES;
    int loc = 0;
    for (int i = beg; i < end; i++) loc += d_degi[i];
    s[t] = loc;
    __syncthreads();
    // Hillis-Steele inclusive scan over 1024 partials
    for (int o = 1; o < 1024; o <<= 1) {
        int v = (t >= o) ? s[t - o] : 0;
        __syncthreads();
        s[t] += v;
        __syncthreads();
    }
    int run = (t > 0) ? s[t - 1] : 0;            // exclusive prefix
    for (int i = beg; i < end; i++) {
        d_off[i] = run;
        d_cur[i] = run;
        run += d_degi[i];
    }
    if (t == 1023) d_off[N_NODES] = s[1023];
}

// ---------------- place edges into dst-sorted source list --------------------
__global__ void k_place(const void* __restrict__ ei) {
    unsigned int e = blockIdx.x * blockDim.x + threadIdx.x;
    if (e >= N_EDGES) return;
    int r = load_edge(ei, e);
    int c = load_edge(ei, N_EDGES + e);
    if ((unsigned)r >= N_NODES || (unsigned)c >= N_NODES) return;
    int pos = atomicAdd(&d_cur[c], 1);
    d_src[pos] = r;
}

// ---------------- layer-1 aggregate + relu:  x1 = relu(dinv*(sum+self)+b1) ---
// 16 threads per node (each owns 4 of 64 channels).
__global__ __launch_bounds__(256) void k_agg1(const float* __restrict__ b1) {
    int tid = threadIdx.x;
    int lane = tid & 15;
    int n = blockIdx.x * 16 + (tid >> 4);
    if (n >= N_NODES) return;
    int s4 = lane * 4;

    const float4* g1 = (const float4*)d_g1;
    float4 s0 = g1[n * 16 + lane];               // self loop term
    float4 s1 = make_float4(0.f, 0.f, 0.f, 0.f);
    int beg = d_off[n], end = d_off[n + 1];
    int i = beg;
    for (; i + 1 < end; i += 2) {
        int a = d_src[i], b = d_src[i + 1];
        float4 va = g1[a * 16 + lane];
        float4 vb = g1[b * 16 + lane];
        s0.x += va.x; s0.y += va.y; s0.z += va.z; s0.w += va.w;
        s1.x += vb.x; s1.y += vb.y; s1.z += vb.z; s1.w += vb.w;
    }
    if (i < end) {
        float4 va = g1[d_src[i] * 16 + lane];
        s0.x += va.x; s0.y += va.y; s0.z += va.z; s0.w += va.w;
    }
    float di = d_dinv[n];
    float4 bb = *(const float4*)&b1[s4];
    float4 r;
    r.x = fmaxf(di * (s0.x + s1.x) + bb.x, 0.f);
    r.y = fmaxf(di * (s0.y + s1.y) + bb.y, 0.f);
    r.z = fmaxf(di * (s0.z + s1.z) + bb.z, 0.f);
    r.w = fmaxf(di * (s0.w + s1.w) + bb.w, 0.f);
    ((float4*)d_x1)[n * 16 + lane] = r;
}

// ---------------- g2 = dinv * (x1 @ W2),  FFMA2, one thread per node ---------
__global__ __launch_bounds__(256) void k_mid(const float* __restrict__ W2) {
    __shared__ float W2T[LOC_OUT][HIDDEN];   // W2T[j][k] = W2[k*16 + j]
    int tid = threadIdx.x;
    for (int i = tid; i < HIDDEN * LOC_OUT; i += 256) {
        int k = i >> 4, j = i & 15;
        W2T[j][k] = W2[i];
    }
    __syncthreads();

    int n = blockIdx.x * 256 + tid;
    if (n >= N_NODES) return;

    unsigned long long xp[32];               // x1 row as 32 packed pairs
    const float4* xx = (const float4*)&d_x1[(size_t)n * HIDDEN];
    #pragma unroll
    for (int q = 0; q < 16; q++) {
        float4 x = xx[q];
        xp[2 * q]     = pack2(x.x, x.y);
        xp[2 * q + 1] = pack2(x.z, x.w);
    }
    float di = d_dinv[n];
    float o[LOC_OUT];
    #pragma unroll
    for (int j = 0; j < LOC_OUT; j++) {
        unsigned long long a0 = 0ULL, a1 = 0ULL;
        const ulonglong2* w = (const ulonglong2*)&W2T[j][0];
        #pragma unroll
        for (int q = 0; q < 16; q++) {
            ulonglong2 wv = w[q];
            fma2(a0, xp[2 * q],     wv.x);
            fma2(a1, xp[2 * q + 1], wv.y);
        }
        float l0, h0, l1, h1;
        unpack2(a0, l0, h0);
        unpack2(a1, l1, h1);
        o[j] = di * ((l0 + h0) + (l1 + h1));
    }
    float4* dst = (float4*)&d_g2[(size_t)n * LOC_OUT];
    dst[0] = make_float4(o[0],  o[1],  o[2],  o[3]);
    dst[1] = make_float4(o[4],  o[5],  o[6],  o[7]);
    dst[2] = make_float4(o[8],  o[9],  o[10], o[11]);
    dst[3] = make_float4(o[12], o[13], o[14], o[15]);
}

// ---------------- layer-2 aggregate:  x2 = dinv*(sum+self) + b2 --------------
// 4 threads per node (each owns 4 of 16 channels).
__global__ __launch_bounds__(256) void k_agg2(const float* __restrict__ b2) {
    int tid = threadIdx.x;
    int lane = tid & 3;
    int n = blockIdx.x * 64 + (tid >> 2);
    if (n >= N_NODES) return;

    const float4* g2 = (const float4*)d_g2;
    float4 s0 = g2[n * 4 + lane];                // self loop term
    float4 s1 = make_float4(0.f, 0.f, 0.f, 0.f);
    int beg = d_off[n], end = d_off[n + 1];
    int i = beg;
    for (; i + 1 < end; i += 2) {
        int a = d_src[i], b = d_src[i + 1];
        float4 va = g2[a * 4 + lane];
        float4 vb = g2[b * 4 + lane];
        s0.x += va.x; s0.y += va.y; s0.z += va.z; s0.w += va.w;
        s1.x += vb.x; s1.y += vb.y; s1.z += vb.z; s1.w += vb.w;
    }
    if (i < end) {
        float4 va = g2[d_src[i] * 4 + lane];
        s0.x += va.x; s0.y += va.y; s0.z += va.z; s0.w += va.w;
    }
    float di = d_dinv[n];
    float4 bb = *(const float4*)&b2[lane * 4];
    float4 r;
    r.x = di * (s0.x + s1.x) + bb.x;
    r.y = di * (s0.y + s1.y) + bb.y;
    r.z = di * (s0.z + s1.z) + bb.z;
    r.w = di * (s0.w + s1.w) + bb.w;
    ((float4*)d_x2)[n * 4 + lane] = r;
}

// ---------------- final: attention pool over {x2, glob} + linear head --------
__global__ __launch_bounds__(256) void k_final(const float* __restrict__ glob,
                                               const float* __restrict__ aw1,
                                               const float* __restrict__ ab1,
                                               const float* __restrict__ aw2,
                                               const float* __restrict__ lw,
                                               const float* __restrict__ lb,
                                               float* __restrict__ out) {
    __shared__ float s_aw1[256], s_ab1[16], s_aw2[16];
    __shared__ float s_lw[LOC_OUT * OUT_CH], s_lb[OUT_CH];
    int tid = threadIdx.x;
    if (tid < 256) s_aw1[tid] = aw1[tid];
    if (tid < 16) { s_ab1[tid] = ab1[tid]; s_aw2[tid] = aw2[tid]; }
    for (int i = tid; i < LOC_OUT * OUT_CH; i += 256) s_lw[i] = lw[i];
    if (tid < OUT_CH) s_lb[tid] = lb[tid];
    __syncthreads();

    int n = blockIdx.x * 256 + tid;
    if (n >= N_NODES) return;
    float z0[16], z1[16];
    const float4* x2 = (const float4*)&d_x2[n * LOC_OUT];
    const float4* gl = (const float4*)&glob[n * LOC_OUT];
    #pragma unroll
    for (int q = 0; q < 4; q++) {
        float4 a = x2[q], e = gl[q];
        z0[q*4+0] = a.x; z0[q*4+1] = a.y; z0[q*4+2] = a.z; z0[q*4+3] = a.w;
        z1[q*4+0] = e.x; z1[q*4+1] = e.y; z1[q*4+2] = e.z; z1[q*4+3] = e.w;
    }
    float w0 = 0.f, w1 = 0.f;
    #pragma unroll
    for (int j = 0; j < 16; j++) {
        float s0 = s_ab1[j], s1 = s_ab1[j];
        #pragma unroll
        for (int i2 = 0; i2 < 16; i2++) {
            s0 += z0[i2] * s_aw1[i2 * 16 + j];
            s1 += z1[i2] * s_aw1[i2 * 16 + j];
        }
        w0 += tanhf(s0) * s_aw2[j];
        w1 += tanhf(s1) * s_aw2[j];
    }
    float beta0 = 1.f / (1.f + expf(w1 - w0));   // softmax over 2 slots
    float beta1 = 1.f - beta0;
    float emb[16];
    #pragma unroll
    for (int i2 = 0; i2 < 16; i2++) emb[i2] = beta0 * z0[i2] + beta1 * z1[i2];
    #pragma unroll
    for (int j = 0; j < OUT_CH; j++) {
        float o = s_lb[j];
        #pragma unroll
        for (int i2 = 0; i2 < 16; i2++) o += emb[i2] * s_lw[i2 * OUT_CH + j];
        out[(size_t)n * OUT_CH + j] = o;
    }
}

// ---------------- launch ------------------------------------------------------
extern "C" void kernel_launch(void* const* d_in, const int* in_sizes, int n_in,
                              void* d_out, int out_size) {
    const float* X    = (const float*)d_in[0];
    const void*  ei   = d_in[1];
    const float* glob = (const float*)d_in[2];
    const float* W1   = (const float*)d_in[3];
    const float* b1   = (const float*)d_in[4];
    const float* W2   = (const float*)d_in[5];
    const float* b2   = (const float*)d_in[6];
    const float* aw1  = (const float*)d_in[7];
    const float* ab1  = (const float*)d_in[8];
    const float* aw2  = (const float*)d_in[9];
    const float* lw   = (const float*)d_in[10];
    const float* lb   = (const float*)d_in[11];
    float* out = (float*)d_out;

    k_init  <<<(N_NODES + 255) / 256, 256>>>();                 // 0
    k_detect<<<1, 256>>>((const int*)ei);                       // 1
    k_count <<<(N_EDGES + 255) / 256, 256>>>(ei);               // 2
    k_gemm1 <<<(N_NODES + BM - 1) / BM, 256>>>(X, W1);          // 3  <- profiled
    k_scan  <<<1, 1024>>>();                                    // 4
    k_place <<<(N_EDGES + 255) / 256, 256>>>(ei);               // 5
    k_agg1  <<<(N_NODES + 15) / 16, 256>>>(b1);                 // 6
    k_mid   <<<(N_NODES + 255) / 256, 256>>>(W2);               // 7
    k_agg2  <<<(N_NODES + 63) / 64, 256>>>(b2);                 // 8
    k_final <<<(N_NODES + 255) / 256, 256>>>(glob, aw1, ab1, aw2, lw, lb, out);  // 9
}

// round 9
// speedup vs baseline: 1.0457x; 1.0457x over previous
#include <cuda_runtime.h>

#define N_NODES 100000
#define N_EDGES 3200000
#define IN_CH   512
#define HIDDEN  64
#define LOC_OUT 16
#define OUT_CH  40

// ---------------- scratch (static device globals; no runtime alloc) ----------
__device__ __align__(16) int   d_degi[N_NODES];            // edge in-degree (no self loop)
__device__ __align__(16) float d_dinv[N_NODES];            // 1/sqrt(deg+1)
__device__ __align__(16) float d_g1  [N_NODES * HIDDEN];   // dinv * (X @ W1)
__device__ __align__(16) float d_g2  [N_NODES * LOC_OUT];  // dinv * (x1 @ W2)
__device__ __align__(16) float d_x2  [N_NODES * LOC_OUT];  // layer-2 output (z0)
__device__ __align__(16) int   d_off [N_NODES + 1];        // CSR offsets (by dst)
__device__ __align__(16) int   d_cur [N_NODES];            // placement cursors
__device__ __align__(16) int   d_src [N_EDGES];            // dst-sorted source ids
__device__ int d_idx_nonzero_odd;   // >0  =>  edge_index is int32

// ---------------- packed f32x2 helpers ---------------------------------------
__device__ __forceinline__ unsigned long long dup2(float a) {
    unsigned long long r;
    asm("mov.b64 %0, {%1, %1};" : "=l"(r) : "f"(a));
    return r;
}
__device__ __forceinline__ void fma2(unsigned long long& d,
                                     unsigned long long a, unsigned long long b) {
    asm("fma.rn.f32x2 %0, %1, %2, %0;" : "+l"(d) : "l"(a), "l"(b));
}
__device__ __forceinline__ void unpack2(unsigned long long v, float& lo, float& hi) {
    asm("mov.b64 {%0, %1}, %2;" : "=f"(lo), "=f"(hi) : "l"(v));
}

// ---------------- edge index fetch: handles int64 or int32 buffers -----------
__device__ __forceinline__ int load_edge(const void* ei, unsigned int pos) {
    if (d_idx_nonzero_odd == 0) {          // int64 payload (high words all 0)
        return (int)((const long long*)ei)[pos];
    } else {                               // int32 payload
        return ((const int*)ei)[pos];
    }
}

// ---------------- dtype detection: sample odd int32 slots --------------------
__global__ void k_detect(const int* __restrict__ ei32) {
    int t = threadIdx.x;
    int nz = 0;
    #pragma unroll
    for (int j = 0; j < 8; j++) nz |= ei32[2 * (t * 8 + j) + 1];
    if (nz) atomicOr(&d_idx_nonzero_odd, 1);
}

// ---------------- init: zero degree histogram + flag -------------------------
__global__ void k_init() {
    int i = blockIdx.x * blockDim.x + threadIdx.x;
    if (i < N_NODES) d_degi[i] = 0;
    if (i == 0)      d_idx_nonzero_odd = 0;
}

// ---------------- degree count over targets (col = edge_index[1]) ------------
__global__ void k_count(const void* __restrict__ ei) {
    unsigned int e = blockIdx.x * blockDim.x + threadIdx.x;
    if (e < N_EDGES) {
        int c = load_edge(ei, N_EDGES + e);
        if ((unsigned)c < N_NODES) atomicAdd(&d_degi[c], 1);
    }
}

// ---------------- GEMM1: g1 = dinv * (X @ W1);  also writes d_dinv -----------
// BM=256 x 64 per block, 256 threads, 8x8/thread, FFMA2, swizzled float4 A tile.
#define BM 256
#define BK 32

__global__ __launch_bounds__(256, 2) void k_gemm1(const float* __restrict__ X,
                                                  const float* __restrict__ W1) {
    __shared__ float4 Xq[BM][8];           // 32 KB, col swizzled: q ^ ((m>>3)&7)
    __shared__ float  Ws[BK * HIDDEN];     // 8 KB, k-major: Ws[k*64 + n]
    int tid = threadIdx.x;
    int tx = tid & 7;          // col group: cols tx*8 .. tx*8+7
    int ty = tid >> 3;         // row group: rows ty*8 .. ty*8+7 (0..31)
    int row0 = blockIdx.x * BM;

    unsigned long long acc[8][4];
    #pragma unroll
    for (int i = 0; i < 8; i++)
        #pragma unroll
        for (int j = 0; j < 4; j++) acc[i][j] = 0ULL;

    for (int k0 = 0; k0 < IN_CH; k0 += BK) {
        // X tile (256 rows x 32 k) as float4 quads, swizzled columns
        #pragma unroll
        for (int it = 0; it < 8; it++) {
            int m = (tid >> 3) + it * 32;      // 0..255
            int q = tid & 7;                   // k-quad 0..7
            int gr = row0 + m;
            float4 v = (gr < N_NODES)
                     ? *(const float4*)&X[(size_t)gr * IN_CH + k0 + q * 4]
                     : make_float4(0.f, 0.f, 0.f, 0.f);
            Xq[m][q ^ ((m >> 3) & 7)] = v;
        }
        // W tile (32 x 64), contiguous float4 copy
        #pragma unroll
        for (int it = 0; it < 2; it++) {
            int f4 = tid + it * 256;
            ((float4*)Ws)[f4] = ((const float4*)&W1[(size_t)k0 * HIDDEN])[f4];
        }
        __syncthreads();

        #pragma unroll
        for (int q = 0; q < 8; q++) {
            int col = q ^ (ty & 7);            // uniform per thread
            float4 Aq[8];
            #pragma unroll
            for (int i = 0; i < 8; i++) Aq[i] = Xq[ty * 8 + i][col];
            #pragma unroll
            for (int kk = 0; kk < 4; kk++) {
                const ulonglong2* bw =
                    (const ulonglong2*)&Ws[(q * 4 + kk) * HIDDEN + tx * 8];
                ulonglong2 bA = bw[0];
                ulonglong2 bB = bw[1];
                #pragma unroll
                for (int i = 0; i < 8; i++) {
                    float a = (kk == 0) ? Aq[i].x : (kk == 1) ? Aq[i].y
                            : (kk == 2) ? Aq[i].z : Aq[i].w;
                    unsigned long long A = dup2(a);
                    fma2(acc[i][0], A, bA.x);
                    fma2(acc[i][1], A, bA.y);
                    fma2(acc[i][2], A, bB.x);
                    fma2(acc[i][3], A, bB.y);
                }
            }
        }
        __syncthreads();
    }

    // epilogue: dinv = rsqrt(deg+1) computed inline; scale + store
    #pragma unroll
    for (int i = 0; i < 8; i++) {
        int r = row0 + ty * 8 + i;
        if (r < N_NODES) {
            float di = rsqrtf((float)(d_degi[r] + 1));
            if (tx == 0) d_dinv[r] = di;
            float o[8];
            #pragma unroll
            for (int j = 0; j < 4; j++) unpack2(acc[i][j], o[2 * j], o[2 * j + 1]);
            float4 v0 = make_float4(di * o[0], di * o[1], di * o[2], di * o[3]);
            float4 v1 = make_float4(di * o[4], di * o[5], di * o[6], di * o[7]);
            float* dst = &d_g1[(size_t)r * HIDDEN + tx * 8];
            *(float4*)dst       = v0;
            *(float4*)(dst + 4) = v1;
        }
    }
}

// ---------------- exclusive scan of degrees -> CSR offsets (1 block) ---------
__global__ __launch_bounds__(1024) void k_scan() {
    __shared__ int s[1024];
    const int C = (N_NODES + 1023) / 1024;       // 98
    int t = threadIdx.x;
    int beg = t * C;
    int end = beg + C; if (end > N_NODES) end = N_NODES;
    int loc = 0;
    for (int i = beg; i < end; i++) loc += d_degi[i];
    s[t] = loc;
    __syncthreads();
    for (int o = 1; o < 1024; o <<= 1) {
        int v = (t >= o) ? s[t - o] : 0;
        __syncthreads();
        s[t] += v;
        __syncthreads();
    }
    int run = (t > 0) ? s[t - 1] : 0;
    for (int i = beg; i < end; i++) {
        d_off[i] = run;
        d_cur[i] = run;
        run += d_degi[i];
    }
    if (t == 1023) d_off[N_NODES] = s[1023];
}

// ---------------- place edges into dst-sorted source list --------------------
__global__ void k_place(const void* __restrict__ ei) {
    unsigned int e = blockIdx.x * blockDim.x + threadIdx.x;
    if (e >= N_EDGES) return;
    int r = load_edge(ei, e);
    int c = load_edge(ei, N_EDGES + e);
    if ((unsigned)r >= N_NODES || (unsigned)c >= N_NODES) return;
    int pos = atomicAdd(&d_cur[c], 1);
    d_src[pos] = r;
}

// ---------------- fused layer-1 aggregate + relu + GEMM2 ---------------------
// 16 nodes per block, 16 threads per node.
// Phase 1: x1[node] = relu(dinv*(sum_nbrs g1 + g1[node]) + b1)  -> smem
// Phase 2: g2[node][j] = dinv * dot(x1[node], W2[:,j])
#define X1_STRIDE 68
#define W2T_STRIDE 65
__global__ __launch_bounds__(256) void k_aggmid(const float* __restrict__ b1,
                                                const float* __restrict__ W2) {
    __shared__ float x1s[16 * X1_STRIDE];        // 16 rows of 64 (+pad)
    __shared__ float w2t[LOC_OUT * W2T_STRIDE];  // W2T[j][k] = W2[k*16+j]
    int tid = threadIdx.x;
    for (int i = tid; i < HIDDEN * LOC_OUT; i += 256) {
        int k = i >> 4, j = i & 15;
        w2t[j * W2T_STRIDE + k] = W2[i];
    }

    int lane = tid & 15;
    int local = tid >> 4;                        // 0..15
    int n = blockIdx.x * 16 + local;
    bool alive = (n < N_NODES);
    float di = 0.f;

    if (alive) {
        const float4* g1 = (const float4*)d_g1;
        float4 s0 = g1[n * 16 + lane];           // self loop term
        float4 s1 = make_float4(0.f, 0.f, 0.f, 0.f);
        int beg = d_off[n], end = d_off[n + 1];
        int i = beg;
        for (; i + 1 < end; i += 2) {
            int a = d_src[i], b = d_src[i + 1];
            float4 va = g1[a * 16 + lane];
            float4 vb = g1[b * 16 + lane];
            s0.x += va.x; s0.y += va.y; s0.z += va.z; s0.w += va.w;
            s1.x += vb.x; s1.y += vb.y; s1.z += vb.z; s1.w += vb.w;
        }
        if (i < end) {
            float4 va = g1[d_src[i] * 16 + lane];
            s0.x += va.x; s0.y += va.y; s0.z += va.z; s0.w += va.w;
        }
        di = d_dinv[n];
        float4 bb = *(const float4*)&b1[lane * 4];
        float* xr = &x1s[local * X1_STRIDE + lane * 4];
        xr[0] = fmaxf(di * (s0.x + s1.x) + bb.x, 0.f);
        xr[1] = fmaxf(di * (s0.y + s1.y) + bb.y, 0.f);
        xr[2] = fmaxf(di * (s0.z + s1.z) + bb.z, 0.f);
        xr[3] = fmaxf(di * (s0.w + s1.w) + bb.w, 0.f);
    }
    __syncthreads();

    if (!alive) return;
    // phase 2: this thread computes output column `lane` for node `n`
    const float* xr = &x1s[local * X1_STRIDE];
    const float* wr = &w2t[lane * W2T_STRIDE];
    float acc = 0.f;
    #pragma unroll
    for (int k = 0; k < HIDDEN; k += 4) {
        float4 x = *(const float4*)&xr[k];       // broadcast across 16 lanes
        acc += x.x * wr[k + 0];
        acc += x.y * wr[k + 1];
        acc += x.z * wr[k + 2];
        acc += x.w * wr[k + 3];
    }
    d_g2[n * LOC_OUT + lane] = di * acc;         // fully coalesced
}

// ---------------- layer-2 aggregate:  x2 = dinv*(sum+self) + b2 --------------
// 4 threads per node (each owns 4 of 16 channels).
__global__ __launch_bounds__(256) void k_agg2(const float* __restrict__ b2) {
    int tid = threadIdx.x;
    int lane = tid & 3;
    int n = blockIdx.x * 64 + (tid >> 2);
    if (n >= N_NODES) return;

    const float4* g2 = (const float4*)d_g2;
    float4 s0 = g2[n * 4 + lane];                // self loop term
    float4 s1 = make_float4(0.f, 0.f, 0.f, 0.f);
    int beg = d_off[n], end = d_off[n + 1];
    int i = beg;
    for (; i + 1 < end; i += 2) {
        int a = d_src[i], b = d_src[i + 1];
        float4 va = g2[a * 4 + lane];
        float4 vb = g2[b * 4 + lane];
        s0.x += va.x; s0.y += va.y; s0.z += va.z; s0.w += va.w;
        s1.x += vb.x; s1.y += vb.y; s1.z += vb.z; s1.w += vb.w;
    }
    if (i < end) {
        float4 va = g2[d_src[i] * 4 + lane];
        s0.x += va.x; s0.y += va.y; s0.z += va.z; s0.w += va.w;
    }
    float di = d_dinv[n];
    float4 bb = *(const float4*)&b2[lane * 4];
    float4 r;
    r.x = di * (s0.x + s1.x) + bb.x;
    r.y = di * (s0.y + s1.y) + bb.y;
    r.z = di * (s0.z + s1.z) + bb.z;
    r.w = di * (s0.w + s1.w) + bb.w;
    ((float4*)d_x2)[n * 4 + lane] = r;
}

// ---------------- final: attention pool over {x2, glob} + linear head --------
__global__ __launch_bounds__(256) void k_final(const float* __restrict__ glob,
                                               const float* __restrict__ aw1,
                                               const float* __restrict__ ab1,
                                               const float* __restrict__ aw2,
                                               const float* __restrict__ lw,
                                               const float* __restrict__ lb,
                                               float* __restrict__ out) {
    __shared__ float s_aw1[256], s_ab1[16], s_aw2[16];
    __shared__ float s_lw[LOC_OUT * OUT_CH], s_lb[OUT_CH];
    int tid = threadIdx.x;
    if (tid < 256) s_aw1[tid] = aw1[tid];
    if (tid < 16) { s_ab1[tid] = ab1[tid]; s_aw2[tid] = aw2[tid]; }
    for (int i = tid; i < LOC_OUT * OUT_CH; i += 256) s_lw[i] = lw[i];
    if (tid < OUT_CH) s_lb[tid] = lb[tid];
    __syncthreads();

    int n = blockIdx.x * 256 + tid;
    if (n >= N_NODES) return;
    float z0[16], z1[16];
    const float4* x2 = (const float4*)&d_x2[n * LOC_OUT];
    const float4* gl = (const float4*)&glob[n * LOC_OUT];
    #pragma unroll
    for (int q = 0; q < 4; q++) {
        float4 a = x2[q], e = gl[q];
        z0[q*4+0] = a.x; z0[q*4+1] = a.y; z0[q*4+2] = a.z; z0[q*4+3] = a.w;
        z1[q*4+0] = e.x; z1[q*4+1] = e.y; z1[q*4+2] = e.z; z1[q*4+3] = e.w;
    }
    float w0 = 0.f, w1 = 0.f;
    #pragma unroll
    for (int j = 0; j < 16; j++) {
        float s0 = s_ab1[j], s1 = s_ab1[j];
        #pragma unroll
        for (int i2 = 0; i2 < 16; i2++) {
            s0 += z0[i2] * s_aw1[i2 * 16 + j];
            s1 += z1[i2] * s_aw1[i2 * 16 + j];
        }
        w0 += tanhf(s0) * s_aw2[j];
        w1 += tanhf(s1) * s_aw2[j];
    }
    float beta0 = 1.f / (1.f + expf(w1 - w0));   // softmax over 2 slots
    float beta1 = 1.f - beta0;
    float emb[16];
    #pragma unroll
    for (int i2 = 0; i2 < 16; i2++) emb[i2] = beta0 * z0[i2] + beta1 * z1[i2];
    #pragma unroll
    for (int j = 0; j < OUT_CH; j++) {
        float o = s_lb[j];
        #pragma unroll
        for (int i2 = 0; i2 < 16; i2++) o += emb[i2] * s_lw[i2 * OUT_CH + j];
        out[(size_t)n * OUT_CH + j] = o;
    }
}

// ---------------- launch ------------------------------------------------------
extern "C" void kernel_launch(void* const* d_in, const int* in_sizes, int n_in,
                              void* d_out, int out_size) {
    const float* X    = (const float*)d_in[0];
    const void*  ei   = d_in[1];
    const float* glob = (const float*)d_in[2];
    const float* W1   = (const float*)d_in[3];
    const float* b1   = (const float*)d_in[4];
    const float* W2   = (const float*)d_in[5];
    const float* b2   = (const float*)d_in[6];
    const float* aw1  = (const float*)d_in[7];
    const float* ab1  = (const float*)d_in[8];
    const float* aw2  = (const float*)d_in[9];
    const float* lw   = (const float*)d_in[10];
    const float* lb   = (const float*)d_in[11];
    float* out = (float*)d_out;

    k_init  <<<(N_NODES + 255) / 256, 256>>>();                 // 0
    k_detect<<<1, 256>>>((const int*)ei);                       // 1
    k_count <<<(N_EDGES + 255) / 256, 256>>>(ei);               // 2
    k_gemm1 <<<(N_NODES + BM - 1) / BM, 256>>>(X, W1);          // 3  <- profiled
    k_scan  <<<1, 1024>>>();                                    // 4
    k_place <<<(N_EDGES + 255) / 256, 256>>>(ei);               // 5
    k_aggmid<<<(N_NODES + 15) / 16, 256>>>(b1, W2);             // 6
    k_agg2  <<<(N_NODES + 63) / 64, 256>>>(b2);                 // 7
    k_final <<<(N_NODES + 255) / 256, 256>>>(glob, aw1, ab1, aw2, lw, lb, out);  // 8
}

// round 12
// speedup vs baseline: 1.2511x; 1.1964x over previous
#include <cuda_runtime.h>
#include <cuda_bf16.h>
#include <cstdint>

#define N_NODES 100000
#define N_EDGES 3200000
#define IN_CH   512
#define HIDDEN  64
#define LOC_OUT 16
#define OUT_CH  40

// ---------------- scratch (static device globals; no runtime alloc) ----------
__device__ __align__(16) int   d_degi[N_NODES];            // edge in-degree (no self loop)
__device__ __align__(16) float d_dinv[N_NODES];            // 1/sqrt(deg+1)
__device__ __align__(16) float d_g1  [N_NODES * HIDDEN];   // dinv * (X @ W1)
__device__ __align__(16) float d_g2  [N_NODES * LOC_OUT];  // dinv * (x1 @ W2)
__device__ __align__(16) float d_x2  [N_NODES * LOC_OUT];  // layer-2 output (z0)
__device__ __align__(16) int   d_off [N_NODES + 1];        // CSR offsets (by dst)
__device__ __align__(16) int   d_cur [N_NODES];            // placement cursors
__device__ __align__(16) int   d_src [N_EDGES];            // dst-sorted source ids
__device__ int d_idx_nonzero_odd;   // >0  =>  edge_index is int32

// ---------------- edge index fetch: handles int64 or int32 buffers -----------
__device__ __forceinline__ int load_edge(const void* ei, unsigned int pos) {
    if (d_idx_nonzero_odd == 0) {          // int64 payload (high words all 0)
        return (int)((const long long*)ei)[pos];
    } else {                               // int32 payload
        return ((const int*)ei)[pos];
    }
}

// ---------------- dtype detection: sample odd int32 slots --------------------
__global__ void k_detect(const int* __restrict__ ei32) {
    int t = threadIdx.x;
    int nz = 0;
    #pragma unroll
    for (int j = 0; j < 8; j++) nz |= ei32[2 * (t * 8 + j) + 1];
    if (nz) atomicOr(&d_idx_nonzero_odd, 1);
}

// ---------------- init: zero degree histogram + flag -------------------------
__global__ void k_init() {
    int i = blockIdx.x * blockDim.x + threadIdx.x;
    if (i < N_NODES) d_degi[i] = 0;
    if (i == 0)      d_idx_nonzero_odd = 0;
}

// ---------------- degree count over targets (col = edge_index[1]) ------------
__global__ void k_count(const void* __restrict__ ei) {
    unsigned int e = blockIdx.x * blockDim.x + threadIdx.x;
    if (e < N_EDGES) {
        int c = load_edge(ei, N_EDGES + e);
        if ((unsigned)c < N_NODES) atomicAdd(&d_degi[c], 1);
    }
}

// ================= mma.sync GEMM1:  g1 = dinv * (X @ W1) =====================
// bf16 split: X = Xh+Xl, W = Wh+Wl; D += Xh*Wh + Xh*Wl + Xl*Wh (fp32 acc).
// CTA: 128 rows x 64 cols, 8 warps (16 rows each). K chunked by 64.
// Smem tiles swizzled with o ^ ((o>>3)&0x70) for conflict-free ldmatrix.

#define SWZ(o) ((o) ^ (((o) >> 3) & 0x70))
#define KC 64

__device__ __forceinline__ uint32_t smem_u32(const void* p) {
    uint32_t a;
    asm("{ .reg .u64 t; cvta.to.shared.u64 t, %1; cvt.u32.u64 %0, t; }"
        : "=r"(a) : "l"(p));
    return a;
}
__device__ __forceinline__ void ldsm_x4(uint32_t* r, uint32_t addr) {
    asm volatile("ldmatrix.sync.aligned.m8n8.x4.shared.b16 {%0,%1,%2,%3}, [%4];"
                 : "=r"(r[0]), "=r"(r[1]), "=r"(r[2]), "=r"(r[3]) : "r"(addr));
}
__device__ __forceinline__ void ldsm_x4_t(uint32_t* r, uint32_t addr) {
    asm volatile("ldmatrix.sync.aligned.m8n8.x4.trans.shared.b16 {%0,%1,%2,%3}, [%4];"
                 : "=r"(r[0]), "=r"(r[1]), "=r"(r[2]), "=r"(r[3]) : "r"(addr));
}
__device__ __forceinline__ void mma16816(float* c, const uint32_t* a,
                                         uint32_t b0, uint32_t b1) {
    asm volatile(
        "mma.sync.aligned.m16n8k16.row.col.f32.bf16.bf16.f32 "
        "{%0,%1,%2,%3}, {%4,%5,%6,%7}, {%8,%9}, {%0,%1,%2,%3};"
        : "+f"(c[0]), "+f"(c[1]), "+f"(c[2]), "+f"(c[3])
        : "r"(a[0]), "r"(a[1]), "r"(a[2]), "r"(a[3]), "r"(b0), "r"(b1));
}
__device__ __forceinline__ uint32_t pack_bf16x2(float a, float b) {
    uint32_t r;
    asm("cvt.rn.bf16x2.f32 %0, %1, %2;" : "=r"(r) : "f"(b), "f"(a));
    return r;
}

__global__ __launch_bounds__(256, 2) void k_gemm1(const float* __restrict__ X,
                                                  const float* __restrict__ W1) {
    __shared__ __align__(16) char sAh[128 * 128];   // 16 KB  (128 rows x 64 bf16)
    __shared__ __align__(16) char sAl[128 * 128];   // 16 KB
    __shared__ __align__(16) char sBh[KC * 128];    // 8 KB   (64 k x 64 bf16)
    __shared__ __align__(16) char sBl[KC * 128];    // 8 KB
    int tid = threadIdx.x;
    int wid = tid >> 5, lane = tid & 31;
    int row0 = blockIdx.x * 128;
    int wr0 = wid * 16;                             // warp's row base in tile

    float acc[8][4];
    #pragma unroll
    for (int i = 0; i < 8; i++)
        #pragma unroll
        for (int j = 0; j < 4; j++) acc[i][j] = 0.f;

    uint32_t aAh = smem_u32(sAh), aAl = smem_u32(sAl);
    uint32_t aBh = smem_u32(sBh), aBl = smem_u32(sBl);

    // precomputed ldmatrix lane addresses (byte offsets within tile)
    uint32_t a_row = (uint32_t)(wr0 + (lane & 15));            // A: row
    uint32_t a_kh  = (uint32_t)((lane >> 4) * 16);             // A: k-half bytes
    uint32_t b_krow = (uint32_t)((lane & 7) + ((lane >> 3) & 1) * 8);  // B: k row
    uint32_t b_nh   = (uint32_t)((lane >> 4) * 16);            // B: n-half bytes

    for (int c = 0; c < IN_CH / KC; c++) {
        int k0 = c * KC;
        // ---- A tile: 128 rows x 64 k fp32 -> bf16 hi/lo, swizzled ------------
        #pragma unroll
        for (int it = 0; it < 8; it++) {
            int idx = it * 256 + tid;              // 0..2047 float4 quads
            int row = idx >> 4;
            int kq = (idx & 15) * 4;
            int gr = row0 + row;
            float4 v = (gr < N_NODES)
                     ? *(const float4*)&X[(size_t)gr * IN_CH + k0 + kq]
                     : make_float4(0.f, 0.f, 0.f, 0.f);
            uint32_t h0 = pack_bf16x2(v.x, v.y);
            uint32_t h1 = pack_bf16x2(v.z, v.w);
            float lx = v.x - __bfloat162float(__ushort_as_bfloat16((unsigned short)(h0 & 0xFFFF)));
            float ly = v.y - __bfloat162float(__ushort_as_bfloat16((unsigned short)(h0 >> 16)));
            float lz = v.z - __bfloat162float(__ushort_as_bfloat16((unsigned short)(h1 & 0xFFFF)));
            float lw = v.w - __bfloat162float(__ushort_as_bfloat16((unsigned short)(h1 >> 16)));
            uint32_t l0 = pack_bf16x2(lx, ly);
            uint32_t l1 = pack_bf16x2(lz, lw);
            uint32_t o = SWZ((uint32_t)(row * 128 + kq * 2));
            *(uint2*)(sAh + o) = make_uint2(h0, h1);
            *(uint2*)(sAl + o) = make_uint2(l0, l1);
        }
        // ---- B tile: 64 k x 64 n fp32 -> bf16 hi/lo, swizzled ----------------
        #pragma unroll
        for (int it = 0; it < 4; it++) {
            int idx = it * 256 + tid;              // 0..1023 float4 quads
            int kk = idx >> 4;
            int n0 = (idx & 15) * 4;
            float4 v = *(const float4*)&W1[(size_t)(k0 + kk) * HIDDEN + n0];
            uint32_t h0 = pack_bf16x2(v.x, v.y);
            uint32_t h1 = pack_bf16x2(v.z, v.w);
            float lx = v.x - __bfloat162float(__ushort_as_bfloat16((unsigned short)(h0 & 0xFFFF)));
            float ly = v.y - __bfloat162float(__ushort_as_bfloat16((unsigned short)(h0 >> 16)));
            float lz = v.z - __bfloat162float(__ushort_as_bfloat16((unsigned short)(h1 & 0xFFFF)));
            float lw = v.w - __bfloat162float(__ushort_as_bfloat16((unsigned short)(h1 >> 16)));
            uint32_t l0 = pack_bf16x2(lx, ly);
            uint32_t l1 = pack_bf16x2(lz, lw);
            uint32_t o = SWZ((uint32_t)(kk * 128 + n0 * 2));
            *(uint2*)(sBh + o) = make_uint2(h0, h1);
            *(uint2*)(sBl + o) = make_uint2(l0, l1);
        }
        __syncthreads();

        #pragma unroll
        for (int k16 = 0; k16 < KC / 16; k16++) {
            uint32_t ao = SWZ(a_row * 128 + (uint32_t)k16 * 32 + a_kh);
            uint32_t ah[4], al[4];
            ldsm_x4(ah, aAh + ao);
            ldsm_x4(al, aAl + ao);
            #pragma unroll
            for (int p = 0; p < 4; p++) {          // n-tile pairs (n16 each)
                uint32_t bo = SWZ(((uint32_t)k16 * 16 + b_krow) * 128
                                  + (uint32_t)p * 32 + b_nh);
                uint32_t bh[4], bl[4];
                ldsm_x4_t(bh, aBh + bo);
                ldsm_x4_t(bl, aBl + bo);
                // ntile 2p
                mma16816(acc[2 * p],     ah, bh[0], bh[1]);
                mma16816(acc[2 * p],     ah, bl[0], bl[1]);
                mma16816(acc[2 * p],     al, bh[0], bh[1]);
                // ntile 2p+1
                mma16816(acc[2 * p + 1], ah, bh[2], bh[3]);
                mma16816(acc[2 * p + 1], ah, bl[2], bl[3]);
                mma16816(acc[2 * p + 1], al, bh[2], bh[3]);
            }
        }
        __syncthreads();
    }

    // ---- epilogue: scale by dinv = rsqrt(deg+1), store; also persist dinv ----
    int gid = lane >> 2, tig = lane & 3;
    int r0 = row0 + wr0 + gid;
    int r1 = r0 + 8;
    float di0 = 0.f, di1 = 0.f;
    if (r0 < N_NODES) di0 = rsqrtf((float)(d_degi[r0] + 1));
    if (r1 < N_NODES) di1 = rsqrtf((float)(d_degi[r1] + 1));
    if (tig == 0) {
        if (r0 < N_NODES) d_dinv[r0] = di0;
        if (r1 < N_NODES) d_dinv[r1] = di1;
    }
    #pragma unroll
    for (int nt = 0; nt < 8; nt++) {
        int col = nt * 8 + tig * 2;
        if (r0 < N_NODES)
            *(float2*)&d_g1[(size_t)r0 * HIDDEN + col] =
                make_float2(di0 * acc[nt][0], di0 * acc[nt][1]);
        if (r1 < N_NODES)
            *(float2*)&d_g1[(size_t)r1 * HIDDEN + col] =
                make_float2(di1 * acc[nt][2], di1 * acc[nt][3]);
    }
}

// ---------------- exclusive scan of degrees -> CSR offsets (1 block) ---------
__global__ __launch_bounds__(1024) void k_scan() {
    __shared__ int s[1024];
    const int C = (N_NODES + 1023) / 1024;       // 98
    int t = threadIdx.x;
    int beg = t * C;
    int end = beg + C; if (end > N_NODES) end = N_NODES;
    int loc = 0;
    for (int i = beg; i < end; i++) loc += d_degi[i];
    s[t] = loc;
    __syncthreads();
    for (int o = 1; o < 1024; o <<= 1) {
        int v = (t >= o) ? s[t - o] : 0;
        __syncthreads();
        s[t] += v;
        __syncthreads();
    }
    int run = (t > 0) ? s[t - 1] : 0;
    for (int i = beg; i < end; i++) {
        d_off[i] = run;
        d_cur[i] = run;
        run += d_degi[i];
    }
    if (t == 1023) d_off[N_NODES] = s[1023];
}

// ---------------- place edges into dst-sorted source list --------------------
__global__ void k_place(const void* __restrict__ ei) {
    unsigned int e = blockIdx.x * blockDim.x + threadIdx.x;
    if (e >= N_EDGES) return;
    int r = load_edge(ei, e);
    int c = load_edge(ei, N_EDGES + e);
    if ((unsigned)r >= N_NODES || (unsigned)c >= N_NODES) return;
    int pos = atomicAdd(&d_cur[c], 1);
    d_src[pos] = r;
}

// ---------------- fused layer-1 aggregate + relu + GEMM2 ---------------------
#define X1_STRIDE 68
#define W2T_STRIDE 65
__global__ __launch_bounds__(256) void k_aggmid(const float* __restrict__ b1,
                                                const float* __restrict__ W2) {
    __shared__ float x1s[16 * X1_STRIDE];        // 16 rows of 64 (+pad)
    __shared__ float w2t[LOC_OUT * W2T_STRIDE];  // W2T[j][k] = W2[k*16+j]
    int tid = threadIdx.x;
    for (int i = tid; i < HIDDEN * LOC_OUT; i += 256) {
        int k = i >> 4, j = i & 15;
        w2t[j * W2T_STRIDE + k] = W2[i];
    }

    int lane = tid & 15;
    int local = tid >> 4;                        // 0..15
    int n = blockIdx.x * 16 + local;
    bool alive = (n < N_NODES);
    float di = 0.f;

    if (alive) {
        const float4* g1 = (const float4*)d_g1;
        float4 s0 = g1[n * 16 + lane];           // self loop term
        float4 s1 = make_float4(0.f, 0.f, 0.f, 0.f);
        int beg = d_off[n], end = d_off[n + 1];
        int i = beg;
        for (; i + 1 < end; i += 2) {
            int a = d_src[i], b = d_src[i + 1];
            float4 va = g1[a * 16 + lane];
            float4 vb = g1[b * 16 + lane];
            s0.x += va.x; s0.y += va.y; s0.z += va.z; s0.w += va.w;
            s1.x += vb.x; s1.y += vb.y; s1.z += vb.z; s1.w += vb.w;
        }
        if (i < end) {
            float4 va = g1[d_src[i] * 16 + lane];
            s0.x += va.x; s0.y += va.y; s0.z += va.z; s0.w += va.w;
        }
        di = d_dinv[n];
        float4 bb = *(const float4*)&b1[lane * 4];
        float* xr = &x1s[local * X1_STRIDE + lane * 4];
        xr[0] = fmaxf(di * (s0.x + s1.x) + bb.x, 0.f);
        xr[1] = fmaxf(di * (s0.y + s1.y) + bb.y, 0.f);
        xr[2] = fmaxf(di * (s0.z + s1.z) + bb.z, 0.f);
        xr[3] = fmaxf(di * (s0.w + s1.w) + bb.w, 0.f);
    }
    __syncthreads();

    if (!alive) return;
    const float* xr = &x1s[local * X1_STRIDE];
    const float* wr = &w2t[lane * W2T_STRIDE];
    float acc = 0.f;
    #pragma unroll
    for (int k = 0; k < HIDDEN; k += 4) {
        float4 x = *(const float4*)&xr[k];       // broadcast across 16 lanes
        acc += x.x * wr[k + 0];
        acc += x.y * wr[k + 1];
        acc += x.z * wr[k + 2];
        acc += x.w * wr[k + 3];
    }
    d_g2[n * LOC_OUT + lane] = di * acc;         // fully coalesced
}

// ---------------- layer-2 aggregate:  x2 = dinv*(sum+self) + b2 --------------
__global__ __launch_bounds__(256) void k_agg2(const float* __restrict__ b2) {
    int tid = threadIdx.x;
    int lane = tid & 3;
    int n = blockIdx.x * 64 + (tid >> 2);
    if (n >= N_NODES) return;

    const float4* g2 = (const float4*)d_g2;
    float4 s0 = g2[n * 4 + lane];                // self loop term
    float4 s1 = make_float4(0.f, 0.f, 0.f, 0.f);
    int beg = d_off[n], end = d_off[n + 1];
    int i = beg;
    for (; i + 1 < end; i += 2) {
        int a = d_src[i], b = d_src[i + 1];
        float4 va = g2[a * 4 + lane];
        float4 vb = g2[b * 4 + lane];
        s0.x += va.x; s0.y += va.y; s0.z += va.z; s0.w += va.w;
        s1.x += vb.x; s1.y += vb.y; s1.z += vb.z; s1.w += vb.w;
    }
    if (i < end) {
        float4 va = g2[d_src[i] * 4 + lane];
        s0.x += va.x; s0.y += va.y; s0.z += va.z; s0.w += va.w;
    }
    float di = d_dinv[n];
    float4 bb = *(const float4*)&b2[lane * 4];
    float4 r;
    r.x = di * (s0.x + s1.x) + bb.x;
    r.y = di * (s0.y + s1.y) + bb.y;
    r.z = di * (s0.z + s1.z) + bb.z;
    r.w = di * (s0.w + s1.w) + bb.w;
    ((float4*)d_x2)[n * 4 + lane] = r;
}

// ---------------- final: attention pool over {x2, glob} + linear head --------
__global__ __launch_bounds__(256) void k_final(const float* __restrict__ glob,
                                               const float* __restrict__ aw1,
                                               const float* __restrict__ ab1,
                                               const float* __restrict__ aw2,
                                               const float* __restrict__ lw,
                                               const float* __restrict__ lb,
                                               float* __restrict__ out) {
    __shared__ float s_aw1[256], s_ab1[16], s_aw2[16];
    __shared__ float s_lw[LOC_OUT * OUT_CH], s_lb[OUT_CH];
    int tid = threadIdx.x;
    if (tid < 256) s_aw1[tid] = aw1[tid];
    if (tid < 16) { s_ab1[tid] = ab1[tid]; s_aw2[tid] = aw2[tid]; }
    for (int i = tid; i < LOC_OUT * OUT_CH; i += 256) s_lw[i] = lw[i];
    if (tid < OUT_CH) s_lb[tid] = lb[tid];
    __syncthreads();

    int n = blockIdx.x * 256 + tid;
    if (n >= N_NODES) return;
    float z0[16], z1[16];
    const float4* x2 = (const float4*)&d_x2[n * LOC_OUT];
    const float4* gl = (const float4*)&glob[n * LOC_OUT];
    #pragma unroll
    for (int q = 0; q < 4; q++) {
        float4 a = x2[q], e = gl[q];
        z0[q*4+0] = a.x; z0[q*4+1] = a.y; z0[q*4+2] = a.z; z0[q*4+3] = a.w;
        z1[q*4+0] = e.x; z1[q*4+1] = e.y; z1[q*4+2] = e.z; z1[q*4+3] = e.w;
    }
    float w0 = 0.f, w1 = 0.f;
    #pragma unroll
    for (int j = 0; j < 16; j++) {
        float s0 = s_ab1[j], s1 = s_ab1[j];
        #pragma unroll
        for (int i2 = 0; i2 < 16; i2++) {
            s0 += z0[i2] * s_aw1[i2 * 16 + j];
            s1 += z1[i2] * s_aw1[i2 * 16 + j];
        }
        w0 += tanhf(s0) * s_aw2[j];
        w1 += tanhf(s1) * s_aw2[j];
    }
    float beta0 = 1.f / (1.f + expf(w1 - w0));   // softmax over 2 slots
    float beta1 = 1.f - beta0;
    float emb[16];
    #pragma unroll
    for (int i2 = 0; i2 < 16; i2++) emb[i2] = beta0 * z0[i2] + beta1 * z1[i2];
    #pragma unroll
    for (int j = 0; j < OUT_CH; j++) {
        float o = s_lb[j];
        #pragma unroll
        for (int i2 = 0; i2 < 16; i2++) o += emb[i2] * s_lw[i2 * OUT_CH + j];
        out[(size_t)n * OUT_CH + j] = o;
    }
}

// ---------------- launch ------------------------------------------------------
extern "C" void kernel_launch(void* const* d_in, const int* in_sizes, int n_in,
                              void* d_out, int out_size) {
    const float* X    = (const float*)d_in[0];
    const void*  ei   = d_in[1];
    const float* glob = (const float*)d_in[2];
    const float* W1   = (const float*)d_in[3];
    const float* b1   = (const float*)d_in[4];
    const float* W2   = (const float*)d_in[5];
    const float* b2   = (const float*)d_in[6];
    const float* aw1  = (const float*)d_in[7];
    const float* ab1  = (const float*)d_in[8];
    const float* aw2  = (const float*)d_in[9];
    const float* lw   = (const float*)d_in[10];
    const float* lb   = (const float*)d_in[11];
    float* out = (float*)d_out;

    k_init  <<<(N_NODES + 255) / 256, 256>>>();                 // 0
    k_detect<<<1, 256>>>((const int*)ei);                       // 1
    k_count <<<(N_EDGES + 255) / 256, 256>>>(ei);               // 2
    k_gemm1 <<<(N_NODES + 127) / 128, 256>>>(X, W1);            // 3  <- profiled
    k_scan  <<<1, 1024>>>();                                    // 4
    k_place <<<(N_EDGES + 255) / 256, 256>>>(ei);               // 5
    k_aggmid<<<(N_NODES + 15) / 16, 256>>>(b1, W2);             // 6
    k_agg2  <<<(N_NODES + 63) / 64, 256>>>(b2);                 // 7
    k_final <<<(N_NODES + 255) / 256, 256>>>(glob, aw1, ab1, aw2, lw, lb, out);  // 8
}